// round 3
// baseline (speedup 1.0000x reference)
#include <cuda_runtime.h>
#include <math.h>

#define NINST 2048

// ---------------- scratch (no allocation allowed -> __device__ globals) ----------------
__device__ float g_F[NINST * 1728];   // CNN features
__device__ float g_H1[NINST * 512];   // fc1 out
__device__ float g_An[NINST * 512];   // tanh(H @ nbr_w^T + b)
__device__ float g_H2[NINST * 1024];  // [:, :512] = H (fc2 out), [:, 512:] = Hn
__device__ float g_P[NINST * 1024];   // tanh(H2 @ proto_w^T + b)
__device__ float g_S[NINST * 10];     // P @ templates^T   (n-major)
__device__ float g_betas[10 * NINST];
__device__ float g_embs[10 * 1024];

__device__ __forceinline__ float warp_sum(float v) {
    #pragma unroll
    for (int o = 16; o; o >>= 1) v += __shfl_xor_sync(0xffffffffu, v, o);
    return v;
}
__device__ __forceinline__ float warp_max(float v) {
    #pragma unroll
    for (int o = 16; o; o >>= 1) v = fmaxf(v, __shfl_xor_sync(0xffffffffu, v, o));
    return v;
}

// ---------------- fused per-instance CNN: conv1+relu+pool, conv2+relu+pool ----------------
// grid = 2048 blocks, 256 threads, ~124KB dynamic smem
__global__ void __launch_bounds__(256) conv_kernel(
    const float* __restrict__ x,
    const float* __restrict__ w1, const float* __restrict__ b1,
    const float* __restrict__ w2, const float* __restrict__ b2)
{
    extern __shared__ float sm[];
    float* xin = sm;            // 1024   (32x32 input)
    float* c1w = sm + 1024;     // 576    (36x1x4x4)
    float* p1  = sm + 1600;     // 7056   (36x14x14 pooled)
    float* w2s = sm + 8656;     // 15552  conv2 weights as [ic][ky][kx][oc]
    float* c2  = sm + 24208;    // 6912   (48x12x12 relu'd conv2)

    const int n = blockIdx.x, tid = threadIdx.x;
    const float* xsrc = x + (size_t)n * 1024;
    for (int i = tid; i < 1024; i += 256) xin[i] = xsrc[i];
    for (int i = tid; i < 576;  i += 256) c1w[i] = w1[i];
    for (int i = tid; i < 15552; i += 256) {
        int oc = i % 48; int r = i / 48;
        int kx = r % 3, ky = (r / 3) % 3, ic = r / 9;
        w2s[i] = w2[oc * 324 + ic * 9 + ky * 3 + kx];
    }
    __syncthreads();

    // conv1 (4x4, VALID -> 29x29) + relu + 2x2 maxpool -> 36 x 14 x 14
    for (int o = tid; o < 7056; o += 256) {
        int c = o / 196, rem = o % 196, py = rem / 14, px = rem % 14;
        int y0 = 2 * py, xx0 = 2 * px;
        float patch[5][5];
        #pragma unroll
        for (int r = 0; r < 5; r++)
            #pragma unroll
            for (int cc = 0; cc < 5; cc++) patch[r][cc] = xin[(y0 + r) * 32 + xx0 + cc];
        const float* wc = &c1w[c * 16];
        float m = -1e30f;
        #pragma unroll
        for (int dy = 0; dy < 2; dy++)
            #pragma unroll
            for (int dx = 0; dx < 2; dx++) {
                float s = 0.f;
                #pragma unroll
                for (int ky = 0; ky < 4; ky++)
                    #pragma unroll
                    for (int kx = 0; kx < 4; kx++)
                        s += patch[dy + ky][dx + kx] * wc[ky * 4 + kx];
                m = fmaxf(m, s);
            }
        p1[o] = fmaxf(m + b1[c], 0.f);  // relu(max(conv)+b) == max(relu(conv+b))
    }
    __syncthreads();

    // conv2 (3x3, 36->48, VALID -> 12x12) + relu, 4-wide-x by 4-oc register blocking
    for (int wk = tid; wk < 432; wk += 256) {
        int ocg = wk / 36, rem = wk % 36, y = rem / 3, xg = rem % 3;
        int oc0 = ocg * 4, xx0 = xg * 4;
        float acc[4][4];
        #pragma unroll
        for (int a = 0; a < 4; a++)
            #pragma unroll
            for (int b = 0; b < 4; b++) acc[a][b] = 0.f;
        for (int ic = 0; ic < 36; ic++) {
            #pragma unroll
            for (int ky = 0; ky < 3; ky++) {
                const float* row = &p1[ic * 196 + (y + ky) * 14 + xx0];
                float in6[6];
                #pragma unroll
                for (int q = 0; q < 6; q++) in6[q] = row[q];
                #pragma unroll
                for (int kx = 0; kx < 3; kx++) {
                    float4 wv = *(const float4*)&w2s[((ic * 3 + ky) * 3 + kx) * 48 + oc0];
                    #pragma unroll
                    for (int xi = 0; xi < 4; xi++) {
                        float v = in6[kx + xi];
                        acc[xi][0] += v * wv.x; acc[xi][1] += v * wv.y;
                        acc[xi][2] += v * wv.z; acc[xi][3] += v * wv.w;
                    }
                }
            }
        }
        #pragma unroll
        for (int oj = 0; oj < 4; oj++) {
            float bb = b2[oc0 + oj];
            #pragma unroll
            for (int xi = 0; xi < 4; xi++)
                c2[(oc0 + oj) * 144 + y * 12 + xx0 + xi] = fmaxf(acc[xi][oj] + bb, 0.f);
        }
    }
    __syncthreads();

    // 2x2 maxpool -> 48x6x6, flatten (c*36 + y*6 + x)
    float* Fo = g_F + (size_t)n * 1728;
    for (int f = tid; f < 1728; f += 256) {
        int c = f / 36, rem = f % 36, py = rem / 6, px = rem % 6;
        int base = c * 144 + 2 * py * 12 + 2 * px;
        Fo[f] = fmaxf(fmaxf(c2[base], c2[base + 1]), fmaxf(c2[base + 12], c2[base + 13]));
    }
}

// ---------------- tiled SGEMM: C[M,N] = act(A[M,K] @ W[N,K]^T + bias) ----------------
// BM=BN=64, BK=16, 256 threads, 4x4 microtile, register-prefetch double buffer.
// M,N mult of 64, K mult of 16. ACT: 0 none, 1 relu, 2 tanh
template <int ACT>
__global__ void __launch_bounds__(256) gemm_kernel(
    const float* __restrict__ A, const float* __restrict__ W,
    const float* __restrict__ bias, float* __restrict__ C,
    int K, int lda, int ldc)
{
    __shared__ float As[16][64];
    __shared__ float Ws[16][64];
    const int tid = threadIdx.x;
    const int tx = tid & 15, ty = tid >> 4;
    const int row0 = blockIdx.y * 64, col0 = blockIdx.x * 64;
    const int lm = tid >> 2, lq = tid & 3;
    const float* Ab = A + (size_t)(row0 + lm) * lda + lq * 4;
    const float* Wb = W + (size_t)(col0 + lm) * K + lq * 4;

    float acc[4][4];
    #pragma unroll
    for (int i = 0; i < 4; i++)
        #pragma unroll
        for (int j = 0; j < 4; j++) acc[i][j] = 0.f;

    // prefetch first tile into registers
    float4 av = *(const float4*)(Ab);
    float4 wv = *(const float4*)(Wb);

    for (int k0 = 0; k0 < K; k0 += 16) {
        As[lq * 4 + 0][lm] = av.x; As[lq * 4 + 1][lm] = av.y;
        As[lq * 4 + 2][lm] = av.z; As[lq * 4 + 3][lm] = av.w;
        Ws[lq * 4 + 0][lm] = wv.x; Ws[lq * 4 + 1][lm] = wv.y;
        Ws[lq * 4 + 2][lm] = wv.z; Ws[lq * 4 + 3][lm] = wv.w;
        __syncthreads();
        // prefetch next tile while computing on the current one
        if (k0 + 16 < K) {
            av = *(const float4*)(Ab + k0 + 16);
            wv = *(const float4*)(Wb + k0 + 16);
        }
        #pragma unroll
        for (int k = 0; k < 16; k++) {
            float4 a = *(const float4*)&As[k][ty * 4];
            float4 b = *(const float4*)&Ws[k][tx * 4];
            acc[0][0] += a.x * b.x; acc[0][1] += a.x * b.y; acc[0][2] += a.x * b.z; acc[0][3] += a.x * b.w;
            acc[1][0] += a.y * b.x; acc[1][1] += a.y * b.y; acc[1][2] += a.y * b.z; acc[1][3] += a.y * b.w;
            acc[2][0] += a.z * b.x; acc[2][1] += a.z * b.y; acc[2][2] += a.z * b.z; acc[2][3] += a.z * b.w;
            acc[3][0] += a.w * b.x; acc[3][1] += a.w * b.y; acc[3][2] += a.w * b.z; acc[3][3] += a.w * b.w;
        }
        __syncthreads();
    }

    float4 bv = *(const float4*)&bias[col0 + tx * 4];
    #pragma unroll
    for (int i = 0; i < 4; i++) {
        float v0 = acc[i][0] + bv.x, v1 = acc[i][1] + bv.y;
        float v2 = acc[i][2] + bv.z, v3 = acc[i][3] + bv.w;
        if (ACT == 1) { v0 = fmaxf(v0, 0.f); v1 = fmaxf(v1, 0.f); v2 = fmaxf(v2, 0.f); v3 = fmaxf(v3, 0.f); }
        if (ACT == 2) { v0 = tanhf(v0); v1 = tanhf(v1); v2 = tanhf(v2); v3 = tanhf(v3); }
        float4 ov = make_float4(v0, v1, v2, v3);
        *(float4*)&C[(size_t)(row0 + ty * 4 + i) * ldc + col0 + tx * 4] = ov;
    }
}

// ---------------- neighbor attention: only the <=8 grid neighbors matter ----------------
// warp per instance; logits[i,j] = H[i] . An[j]; softmax over neighbors; Hn[i] = sum a_j H[j]
__global__ void __launch_bounds__(256) nbr_kernel(const int* __restrict__ positions)
{
    const int warp = threadIdx.x >> 5, lane = threadIdx.x & 31;
    const int i = blockIdx.x * 8 + warp;
    if (i >= NINST) return;
    const int pr = positions[2 * i], pc = positions[2 * i + 1];

    float hi[16];
    #pragma unroll
    for (int q = 0; q < 16; q++) hi[q] = g_H2[(size_t)i * 1024 + lane + q * 32];

    const int dr[8] = {-1, -1, -1, 0, 0, 1, 1, 1};
    const int dc[8] = {-1, 0, 1, -1, 1, -1, 0, 1};
    float lg[8]; int js[8]; int cnt = 0;
    for (int d = 0; d < 8; d++) {
        int nr = pr + dr[d], nc = pc + dc[d];
        if (nr < 0 || nr >= 32 || nc < 0 || nc >= 64) continue;
        int j = nr * 64 + nc;
        const float* an = &g_An[(size_t)j * 512];
        float s = 0.f;
        #pragma unroll
        for (int q = 0; q < 16; q++) s += hi[q] * an[lane + q * 32];
        s = warp_sum(s);
        js[cnt] = j; lg[cnt] = s; cnt++;
    }
    if (cnt == 0) {  // fallback (dead code for this grid, kept for faithfulness)
        const float* an = &g_An[(size_t)i * 512];
        float s = 0.f;
        #pragma unroll
        for (int q = 0; q < 16; q++) s += hi[q] * an[lane + q * 32];
        lg[0] = warp_sum(s); js[0] = i; cnt = 1;
    }
    float m = -1e30f;
    for (int d = 0; d < cnt; d++) m = fmaxf(m, lg[d]);
    float ssum = 0.f;
    for (int d = 0; d < cnt; d++) { lg[d] = expf(lg[d] - m); ssum += lg[d]; }
    float inv = 1.f / ssum;
    #pragma unroll
    for (int q = 0; q < 16; q++) {
        int k = lane + q * 32;
        float a = 0.f;
        for (int d = 0; d < cnt; d++) a += lg[d] * g_H2[(size_t)js[d] * 1024 + k];
        g_H2[(size_t)i * 1024 + 512 + k] = a * inv;
    }
}

// ---------------- S[n][t] = P[n] . templates[t]  (TEMP folded in) ----------------
__global__ void __launch_bounds__(256) s_kernel(const float* __restrict__ tmpl)
{
    const int n = blockIdx.x, tid = threadIdx.x;
    float s[10];
    #pragma unroll
    for (int t = 0; t < 10; t++) s[t] = 0.f;
    for (int k = tid; k < 1024; k += 256) {
        float p = g_P[(size_t)n * 1024 + k];
        #pragma unroll
        for (int t = 0; t < 10; t++) s[t] += p * __ldg(&tmpl[t * 1024 + k]);
    }
    __shared__ float red[8][10];
    #pragma unroll
    for (int t = 0; t < 10; t++) s[t] = warp_sum(s[t]);
    if ((tid & 31) == 0) {
        #pragma unroll
        for (int t = 0; t < 10; t++) red[tid >> 5][t] = s[t];
    }
    __syncthreads();
    if (tid < 10) {
        float v = 0.f;
        #pragma unroll
        for (int w = 0; w < 8; w++) v += red[w][tid];
        g_S[n * 10 + tid] = v;  // / TEMP (== 1.0)
    }
}

// ---------------- betas[t][:] = softmax_n(S[:,t]) ----------------
__global__ void __launch_bounds__(256) betas_kernel()
{
    const int t = blockIdx.x, tid = threadIdx.x;
    __shared__ float red[32];
    float m = -1e30f;
    for (int n = tid; n < NINST; n += 256) m = fmaxf(m, g_S[n * 10 + t]);
    m = warp_max(m);
    if ((tid & 31) == 0) red[tid >> 5] = m;
    __syncthreads();
    if (tid < 32) { float v = (tid < 8) ? red[tid] : -1e30f; v = warp_max(v); if (tid == 0) red[0] = v; }
    __syncthreads();
    m = red[0];
    __syncthreads();
    float s = 0.f;
    for (int n = tid; n < NINST; n += 256) {
        float e = expf(g_S[n * 10 + t] - m);
        g_betas[t * NINST + n] = e;
        s += e;
    }
    s = warp_sum(s);
    if ((tid & 31) == 0) red[tid >> 5] = s;
    __syncthreads();
    if (tid < 32) { float v = (tid < 8) ? red[tid] : 0.f; v = warp_sum(v); if (tid == 0) red[0] = v; }
    __syncthreads();
    float inv = 1.f / red[0];
    for (int n = tid; n < NINST; n += 256) g_betas[t * NINST + n] *= inv;
}

// ---------------- embs[t] = betas[t] @ H2 ----------------
__global__ void __launch_bounds__(256) embs_kernel()
{
    const int t = blockIdx.y;
    const int k = blockIdx.x * 256 + threadIdx.x;
    __shared__ float bsh[256];
    float acc = 0.f;
    for (int n0 = 0; n0 < NINST; n0 += 256) {
        __syncthreads();
        bsh[threadIdx.x] = g_betas[t * NINST + n0 + threadIdx.x];
        __syncthreads();
        #pragma unroll 4
        for (int nn = 0; nn < 256; nn++) acc += bsh[nn] * g_H2[(size_t)(n0 + nn) * 1024 + k];
    }
    g_embs[t * 1024 + k] = acc;
}

// ---------------- global attention + classifier + outputs ----------------
__global__ void __launch_bounds__(256) final_kernel(
    const float* __restrict__ glob_w1, const float* __restrict__ glob_b1,
    const float* __restrict__ glob_w2, const float* __restrict__ glob_b2,
    const float* __restrict__ cls_w, const float* __restrict__ cls_b,
    float* __restrict__ out, int a_off, int out_size)
{
    const int tid = threadIdx.x, warp = tid >> 5, lane = tid & 31;
    __shared__ float gacc[10];
    __shared__ float gam[10];
    __shared__ float Msh[1024];
    __shared__ float r0s[8], r1s[8];
    if (tid < 10) gacc[tid] = 0.f;
    __syncthreads();

    for (int t = 0; t < 10; t++) {
        const float* e = &g_embs[t * 1024];
        for (int o = warp; o < 128; o += 8) {
            const float* wrow = &glob_w1[o * 1024];
            float s = 0.f;
            for (int k = lane; k < 1024; k += 32) s += e[k] * wrow[k];
            s = warp_sum(s);
            if (lane == 0) atomicAdd(&gacc[t], tanhf(s + glob_b1[o]) * glob_w2[o]);
        }
    }
    __syncthreads();
    if (tid == 0) {
        float g[10], m = -1e30f;
        for (int t = 0; t < 10; t++) { g[t] = gacc[t] + glob_b2[0]; m = fmaxf(m, g[t]); }
        float s = 0.f;
        for (int t = 0; t < 10; t++) { g[t] = expf(g[t] - m); s += g[t]; }
        for (int t = 0; t < 10; t++) gam[t] = g[t] / s;
    }
    __syncthreads();

    for (int k = tid; k < 1024; k += 256) {
        float m2 = 0.f;
        #pragma unroll
        for (int t = 0; t < 10; t++) m2 += gam[t] * g_embs[t * 1024 + k];
        Msh[k] = m2;
    }
    if (a_off >= 0) {
        for (int n = tid; n < NINST; n += 256) {
            float a = 0.f;
            #pragma unroll
            for (int t = 0; t < 10; t++) a += gam[t] * g_betas[t * NINST + n];
            out[a_off + n] = a;
        }
    }
    __syncthreads();

    float l0 = 0.f, l1 = 0.f;
    for (int k = tid; k < 1024; k += 256) {
        float mv = Msh[k];
        l0 += mv * cls_w[k];
        l1 += mv * cls_w[1024 + k];
    }
    l0 = warp_sum(l0); l1 = warp_sum(l1);
    if (lane == 0) { r0s[warp] = l0; r1s[warp] = l1; }
    __syncthreads();
    if (tid == 0) {
        float L0 = cls_b[0], L1 = cls_b[1];
        for (int w = 0; w < 8; w++) { L0 += r0s[w]; L1 += r1s[w]; }
        float p0 = 1.f / (1.f + expf(-L0));
        float p1 = 1.f / (1.f + expf(-L1));
        out[0] = p0;
        if (out_size > 1) out[1] = p1;
        if (out_size > 2) out[2] = (p1 > p0) ? 1.f : 0.f;  // argmax (first-max on tie)
    }
}

// ---------------- launch ----------------
extern "C" void kernel_launch(void* const* d_in, const int* in_sizes, int n_in,
                              void* d_out, int out_size)
{
    const float* x       = (const float*)d_in[0];
    const int*   pos     = (const int*)  d_in[1];
    const float* conv1_w = (const float*)d_in[2];
    const float* conv1_b = (const float*)d_in[3];
    const float* conv2_w = (const float*)d_in[4];
    const float* conv2_b = (const float*)d_in[5];
    const float* fc1_w   = (const float*)d_in[6];
    const float* fc1_b   = (const float*)d_in[7];
    const float* fc2_w   = (const float*)d_in[8];
    const float* fc2_b   = (const float*)d_in[9];
    const float* nbr_w   = (const float*)d_in[10];
    const float* nbr_b   = (const float*)d_in[11];
    const float* tmpl    = (const float*)d_in[12];
    const float* proto_w = (const float*)d_in[13];
    const float* proto_b = (const float*)d_in[14];
    const float* glob_w1 = (const float*)d_in[15];
    const float* glob_b1 = (const float*)d_in[16];
    const float* glob_w2 = (const float*)d_in[17];
    const float* glob_b2 = (const float*)d_in[18];
    const float* cls_w   = (const float*)d_in[19];
    const float* cls_b   = (const float*)d_in[20];

    float *pF, *pH1, *pAn, *pH2, *pP;
    cudaGetSymbolAddress((void**)&pF,  g_F);
    cudaGetSymbolAddress((void**)&pH1, g_H1);
    cudaGetSymbolAddress((void**)&pAn, g_An);
    cudaGetSymbolAddress((void**)&pH2, g_H2);
    cudaGetSymbolAddress((void**)&pP,  g_P);

    const int conv_smem = 31120 * 4;  // 124480 B
    cudaFuncSetAttribute(conv_kernel, cudaFuncAttributeMaxDynamicSharedMemorySize, conv_smem);

    conv_kernel<<<NINST, 256, conv_smem>>>(x, conv1_w, conv1_b, conv2_w, conv2_b);

    // fc1: relu(F @ fc1_w^T + b) -> H1
    gemm_kernel<1><<<dim3(512 / 64, NINST / 64), 256>>>(pF, fc1_w, fc1_b, pH1, 1728, 1728, 512);
    // fc2: relu(H1 @ fc2_w^T + b) -> H2[:, :512]
    gemm_kernel<1><<<dim3(512 / 64, NINST / 64), 256>>>(pH1, fc2_w, fc2_b, pH2, 512, 512, 1024);
    // An = tanh(H @ nbr_w^T + b)
    gemm_kernel<2><<<dim3(512 / 64, NINST / 64), 256>>>(pH2, nbr_w, nbr_b, pAn, 512, 1024, 512);
    // neighbor attention -> H2[:, 512:]
    nbr_kernel<<<NINST / 8, 256>>>(pos);
    // P = tanh(H2 @ proto_w^T + b)
    gemm_kernel<2><<<dim3(1024 / 64, NINST / 64), 256>>>(pH2, proto_w, proto_b, pP, 1024, 1024, 1024);
    // S, betas, embs
    s_kernel<<<NINST, 256>>>(tmpl);
    betas_kernel<<<10, 256>>>();
    embs_kernel<<<dim3(4, 10), 256>>>();
    // global attention + classifier + write outputs
    final_kernel<<<1, 256>>>(glob_w1, glob_b1, glob_w2, glob_b2, cls_w, cls_b,
                             (float*)d_out, out_size - NINST, out_size);
}

// round 4
// speedup vs baseline: 1.2526x; 1.2526x over previous
#include <cuda_runtime.h>
#include <math.h>

#define NINST 2048

// ---------------- scratch (no allocation allowed -> __device__ globals) ----------------
__device__ float g_F[NINST * 1728];   // CNN features
__device__ float g_H1[NINST * 512];   // fc1 out
__device__ float g_An[NINST * 512];   // tanh(H @ nbr_w^T + b)
__device__ float g_H2[NINST * 1024];  // [:, :512] = H (fc2 out), [:, 512:] = Hn
__device__ float g_P[NINST * 1024];   // tanh(H2 @ proto_w^T + b)
__device__ float g_S[NINST * 10];     // P @ templates^T   (n-major)
__device__ float g_betas[10 * NINST];
__device__ float g_embs[10 * 1024];
__device__ float g_w2t[15552];        // conv2 weights transposed to [ic][ky][kx][oc]

__device__ __forceinline__ float warp_sum(float v) {
    #pragma unroll
    for (int o = 16; o; o >>= 1) v += __shfl_xor_sync(0xffffffffu, v, o);
    return v;
}
__device__ __forceinline__ float warp_max(float v) {
    #pragma unroll
    for (int o = 16; o; o >>= 1) v = fmaxf(v, __shfl_xor_sync(0xffffffffu, v, o));
    return v;
}

// ---------------- one-shot conv2 weight transpose: [oc][ic][ky][kx] -> [ic][ky][kx][oc] ----------------
__global__ void w2t_kernel(const float* __restrict__ w2)
{
    int i = blockIdx.x * 256 + threadIdx.x;
    if (i < 15552) {
        int oc = i % 48; int r = i / 48;
        int kx = r % 3, ky = (r / 3) % 3, ic = r / 9;
        g_w2t[i] = w2[oc * 324 + ic * 9 + ky * 3 + kx];
    }
}

// ---------------- fused per-instance CNN: conv1+relu+pool, conv2+relu+pool(in regs) ----------------
// grid = 2048 blocks, 256 threads, 96.8KB dynamic smem -> 2 blocks/SM
__global__ void __launch_bounds__(256) conv_kernel(
    const float* __restrict__ x,
    const float* __restrict__ w1, const float* __restrict__ b1,
    const float* __restrict__ b2)
{
    extern __shared__ float sm[];
    float* xin = sm;            // 1024   (32x32 input)
    float* c1w = sm + 1024;     // 576    (36x1x4x4)
    float* p1  = sm + 1600;     // 7056   (36x14x14 pooled)
    float* w2s = sm + 8656;     // 15552  conv2 weights [ic][ky][kx][oc] (pre-transposed)

    const int n = blockIdx.x, tid = threadIdx.x;
    const float* xsrc = x + (size_t)n * 1024;
    for (int i = tid; i < 1024; i += 256) xin[i] = xsrc[i];
    for (int i = tid; i < 576;  i += 256) c1w[i] = w1[i];
    for (int i = tid; i < 15552; i += 256) w2s[i] = g_w2t[i];
    __syncthreads();

    // conv1 (4x4, VALID -> 29x29) + relu + 2x2 maxpool -> 36 x 14 x 14
    for (int o = tid; o < 7056; o += 256) {
        int c = o / 196, rem = o % 196, py = rem / 14, px = rem % 14;
        int y0 = 2 * py, xx0 = 2 * px;
        float patch[5][5];
        #pragma unroll
        for (int r = 0; r < 5; r++)
            #pragma unroll
            for (int cc = 0; cc < 5; cc++) patch[r][cc] = xin[(y0 + r) * 32 + xx0 + cc];
        const float* wc = &c1w[c * 16];
        float m = -1e30f;
        #pragma unroll
        for (int dy = 0; dy < 2; dy++)
            #pragma unroll
            for (int dx = 0; dx < 2; dx++) {
                float s = 0.f;
                #pragma unroll
                for (int ky = 0; ky < 4; ky++)
                    #pragma unroll
                    for (int kx = 0; kx < 4; kx++)
                        s += patch[dy + ky][dx + kx] * wc[ky * 4 + kx];
                m = fmaxf(m, s);
            }
        p1[o] = fmaxf(m + b1[c], 0.f);  // relu(max(conv)+b) == max(relu(conv+b))
    }
    __syncthreads();

    // conv2 (3x3, 36->48, VALID -> 12x12) + relu + 2x2 maxpool, fully in registers.
    // 216 items: each computes 2 conv rows x 4 conv cols x 4 ocs -> 2x4=8 pooled outputs.
    if (tid < 216) {
        const int ocg = tid / 18, rem = tid % 18, py = rem / 3, xg = rem % 3;
        const int oc0 = ocg * 4, y0 = 2 * py, x0 = 4 * xg;
        float acc[2][4][4];  // [yy][xi][oj]
        #pragma unroll
        for (int yy = 0; yy < 2; yy++)
            #pragma unroll
            for (int xi = 0; xi < 4; xi++)
                #pragma unroll
                for (int oj = 0; oj < 4; oj++) acc[yy][xi][oj] = 0.f;

        for (int ic = 0; ic < 36; ic++) {
            float in[4][6];
            #pragma unroll
            for (int r = 0; r < 4; r++) {
                const float* row = &p1[ic * 196 + (y0 + r) * 14 + x0];
                #pragma unroll
                for (int c = 0; c < 6; c++) in[r][c] = row[c];
            }
            #pragma unroll
            for (int ky = 0; ky < 3; ky++) {
                #pragma unroll
                for (int kx = 0; kx < 3; kx++) {
                    float4 wv = *(const float4*)&w2s[((ic * 3 + ky) * 3 + kx) * 48 + oc0];
                    #pragma unroll
                    for (int yy = 0; yy < 2; yy++)
                        #pragma unroll
                        for (int xi = 0; xi < 4; xi++) {
                            float v = in[yy + ky][kx + xi];
                            acc[yy][xi][0] += v * wv.x; acc[yy][xi][1] += v * wv.y;
                            acc[yy][xi][2] += v * wv.z; acc[yy][xi][3] += v * wv.w;
                        }
                }
            }
        }
        // bias + relu + pool, write flattened (c*36 + y*6 + x)
        float* Fo = g_F + (size_t)n * 1728;
        #pragma unroll
        for (int oj = 0; oj < 4; oj++) {
            float bb = b2[oc0 + oj];
            #pragma unroll
            for (int px = 0; px < 2; px++) {
                float m = fmaxf(fmaxf(acc[0][2 * px][oj], acc[0][2 * px + 1][oj]),
                                fmaxf(acc[1][2 * px][oj], acc[1][2 * px + 1][oj]));
                Fo[(oc0 + oj) * 36 + py * 6 + 2 * xg + px] = fmaxf(m + bb, 0.f);
            }
        }
    }
}

// ---------------- tiled SGEMM: C[M,N] = act(A[M,K] @ W[N,K]^T + bias) ----------------
// BM=128, BN=64, BK=16, 256 threads, 8x4 microtile, register-prefetch double buffer.
// M mult of 128, N mult of 64, K mult of 16. ACT: 0 none, 1 relu, 2 tanh
template <int ACT>
__global__ void __launch_bounds__(256) gemm_kernel(
    const float* __restrict__ A, const float* __restrict__ W,
    const float* __restrict__ bias, float* __restrict__ C,
    int K, int lda, int ldc)
{
    __shared__ float As[16][132];   // padded, 132*4 % 16 == 0 keeps float4 alignment
    __shared__ float Ws[16][68];
    const int tid = threadIdx.x;
    const int tx = tid & 15, ty = tid >> 4;
    const int row0 = blockIdx.y * 128, col0 = blockIdx.x * 64;
    const int lm = tid >> 2;            // 0..63
    const int lk = (tid & 3) * 4;       // 0,4,8,12
    const float* Ab0 = A + (size_t)(row0 + lm) * lda + lk;
    const float* Ab1 = A + (size_t)(row0 + lm + 64) * lda + lk;
    const float* Wb  = W + (size_t)(col0 + lm) * K + lk;

    float acc[8][4];
    #pragma unroll
    for (int i = 0; i < 8; i++)
        #pragma unroll
        for (int j = 0; j < 4; j++) acc[i][j] = 0.f;

    // prefetch first tile
    float4 av0 = *(const float4*)(Ab0);
    float4 av1 = *(const float4*)(Ab1);
    float4 wv  = *(const float4*)(Wb);

    for (int k0 = 0; k0 < K; k0 += 16) {
        As[lk + 0][lm] = av0.x; As[lk + 1][lm] = av0.y; As[lk + 2][lm] = av0.z; As[lk + 3][lm] = av0.w;
        As[lk + 0][lm + 64] = av1.x; As[lk + 1][lm + 64] = av1.y; As[lk + 2][lm + 64] = av1.z; As[lk + 3][lm + 64] = av1.w;
        Ws[lk + 0][lm] = wv.x; Ws[lk + 1][lm] = wv.y; Ws[lk + 2][lm] = wv.z; Ws[lk + 3][lm] = wv.w;
        __syncthreads();
        if (k0 + 16 < K) {
            av0 = *(const float4*)(Ab0 + k0 + 16);
            av1 = *(const float4*)(Ab1 + k0 + 16);
            wv  = *(const float4*)(Wb  + k0 + 16);
        }
        #pragma unroll
        for (int k = 0; k < 16; k++) {
            float4 a0 = *(const float4*)&As[k][ty * 8];
            float4 a1 = *(const float4*)&As[k][ty * 8 + 4];
            float4 b  = *(const float4*)&Ws[k][tx * 4];
            float ar[8] = {a0.x, a0.y, a0.z, a0.w, a1.x, a1.y, a1.z, a1.w};
            #pragma unroll
            for (int i = 0; i < 8; i++) {
                acc[i][0] += ar[i] * b.x; acc[i][1] += ar[i] * b.y;
                acc[i][2] += ar[i] * b.z; acc[i][3] += ar[i] * b.w;
            }
        }
        __syncthreads();
    }

    float4 bv = *(const float4*)&bias[col0 + tx * 4];
    #pragma unroll
    for (int i = 0; i < 8; i++) {
        float v0 = acc[i][0] + bv.x, v1 = acc[i][1] + bv.y;
        float v2 = acc[i][2] + bv.z, v3 = acc[i][3] + bv.w;
        if (ACT == 1) { v0 = fmaxf(v0, 0.f); v1 = fmaxf(v1, 0.f); v2 = fmaxf(v2, 0.f); v3 = fmaxf(v3, 0.f); }
        if (ACT == 2) { v0 = tanhf(v0); v1 = tanhf(v1); v2 = tanhf(v2); v3 = tanhf(v3); }
        float4 ov = make_float4(v0, v1, v2, v3);
        *(float4*)&C[(size_t)(row0 + ty * 8 + i) * ldc + col0 + tx * 4] = ov;
    }
}

// ---------------- neighbor attention: only the <=8 grid neighbors matter ----------------
// warp per instance; logits[i,j] = H[i] . An[j]; softmax over neighbors; Hn[i] = sum a_j H[j]
__global__ void __launch_bounds__(256) nbr_kernel(const int* __restrict__ positions)
{
    const int warp = threadIdx.x >> 5, lane = threadIdx.x & 31;
    const int i = blockIdx.x * 8 + warp;
    if (i >= NINST) return;
    const int pr = positions[2 * i], pc = positions[2 * i + 1];

    float hi[16];
    #pragma unroll
    for (int q = 0; q < 16; q++) hi[q] = g_H2[(size_t)i * 1024 + lane + q * 32];

    const int dr[8] = {-1, -1, -1, 0, 0, 1, 1, 1};
    const int dc[8] = {-1, 0, 1, -1, 1, -1, 0, 1};
    float lg[8]; int js[8]; int cnt = 0;
    for (int d = 0; d < 8; d++) {
        int nr = pr + dr[d], nc = pc + dc[d];
        if (nr < 0 || nr >= 32 || nc < 0 || nc >= 64) continue;
        int j = nr * 64 + nc;
        const float* an = &g_An[(size_t)j * 512];
        float s = 0.f;
        #pragma unroll
        for (int q = 0; q < 16; q++) s += hi[q] * an[lane + q * 32];
        s = warp_sum(s);
        js[cnt] = j; lg[cnt] = s; cnt++;
    }
    if (cnt == 0) {  // fallback (dead code for this grid, kept for faithfulness)
        const float* an = &g_An[(size_t)i * 512];
        float s = 0.f;
        #pragma unroll
        for (int q = 0; q < 16; q++) s += hi[q] * an[lane + q * 32];
        lg[0] = warp_sum(s); js[0] = i; cnt = 1;
    }
    float m = -1e30f;
    for (int d = 0; d < cnt; d++) m = fmaxf(m, lg[d]);
    float ssum = 0.f;
    for (int d = 0; d < cnt; d++) { lg[d] = expf(lg[d] - m); ssum += lg[d]; }
    float inv = 1.f / ssum;
    #pragma unroll
    for (int q = 0; q < 16; q++) {
        int k = lane + q * 32;
        float a = 0.f;
        for (int d = 0; d < cnt; d++) a += lg[d] * g_H2[(size_t)js[d] * 1024 + k];
        g_H2[(size_t)i * 1024 + 512 + k] = a * inv;
    }
}

// ---------------- S[n][t] = P[n] . templates[t]  (TEMP folded in) ----------------
__global__ void __launch_bounds__(256) s_kernel(const float* __restrict__ tmpl)
{
    const int n = blockIdx.x, tid = threadIdx.x;
    float s[10];
    #pragma unroll
    for (int t = 0; t < 10; t++) s[t] = 0.f;
    for (int k = tid; k < 1024; k += 256) {
        float p = g_P[(size_t)n * 1024 + k];
        #pragma unroll
        for (int t = 0; t < 10; t++) s[t] += p * __ldg(&tmpl[t * 1024 + k]);
    }
    __shared__ float red[8][10];
    #pragma unroll
    for (int t = 0; t < 10; t++) s[t] = warp_sum(s[t]);
    if ((tid & 31) == 0) {
        #pragma unroll
        for (int t = 0; t < 10; t++) red[tid >> 5][t] = s[t];
    }
    __syncthreads();
    if (tid < 10) {
        float v = 0.f;
        #pragma unroll
        for (int w = 0; w < 8; w++) v += red[w][tid];
        g_S[n * 10 + tid] = v;  // / TEMP (== 1.0)
    }
}

// ---------------- betas[t][:] = softmax_n(S[:,t]) ----------------
__global__ void __launch_bounds__(256) betas_kernel()
{
    const int t = blockIdx.x, tid = threadIdx.x;
    __shared__ float red[32];
    float m = -1e30f;
    for (int n = tid; n < NINST; n += 256) m = fmaxf(m, g_S[n * 10 + t]);
    m = warp_max(m);
    if ((tid & 31) == 0) red[tid >> 5] = m;
    __syncthreads();
    if (tid < 32) { float v = (tid < 8) ? red[tid] : -1e30f; v = warp_max(v); if (tid == 0) red[0] = v; }
    __syncthreads();
    m = red[0];
    __syncthreads();
    float s = 0.f;
    for (int n = tid; n < NINST; n += 256) {
        float e = expf(g_S[n * 10 + t] - m);
        g_betas[t * NINST + n] = e;
        s += e;
    }
    s = warp_sum(s);
    if ((tid & 31) == 0) red[tid >> 5] = s;
    __syncthreads();
    if (tid < 32) { float v = (tid < 8) ? red[tid] : 0.f; v = warp_sum(v); if (tid == 0) red[0] = v; }
    __syncthreads();
    float inv = 1.f / red[0];
    for (int n = tid; n < NINST; n += 256) g_betas[t * NINST + n] *= inv;
}

// ---------------- embs[t] = betas[t] @ H2 ----------------
__global__ void __launch_bounds__(256) embs_kernel()
{
    const int t = blockIdx.y;
    const int k = blockIdx.x * 256 + threadIdx.x;
    __shared__ float bsh[256];
    float acc = 0.f;
    for (int n0 = 0; n0 < NINST; n0 += 256) {
        __syncthreads();
        bsh[threadIdx.x] = g_betas[t * NINST + n0 + threadIdx.x];
        __syncthreads();
        #pragma unroll 4
        for (int nn = 0; nn < 256; nn++) acc += bsh[nn] * g_H2[(size_t)(n0 + nn) * 1024 + k];
    }
    g_embs[t * 1024 + k] = acc;
}

// ---------------- global attention + classifier + outputs ----------------
__global__ void __launch_bounds__(256) final_kernel(
    const float* __restrict__ glob_w1, const float* __restrict__ glob_b1,
    const float* __restrict__ glob_w2, const float* __restrict__ glob_b2,
    const float* __restrict__ cls_w, const float* __restrict__ cls_b,
    float* __restrict__ out, int a_off, int out_size)
{
    const int tid = threadIdx.x, warp = tid >> 5, lane = tid & 31;
    __shared__ float gacc[10];
    __shared__ float gam[10];
    __shared__ float Msh[1024];
    __shared__ float r0s[8], r1s[8];
    if (tid < 10) gacc[tid] = 0.f;
    __syncthreads();

    for (int t = 0; t < 10; t++) {
        const float* e = &g_embs[t * 1024];
        for (int o = warp; o < 128; o += 8) {
            const float* wrow = &glob_w1[o * 1024];
            float s = 0.f;
            for (int k = lane; k < 1024; k += 32) s += e[k] * wrow[k];
            s = warp_sum(s);
            if (lane == 0) atomicAdd(&gacc[t], tanhf(s + glob_b1[o]) * glob_w2[o]);
        }
    }
    __syncthreads();
    if (tid == 0) {
        float g[10], m = -1e30f;
        for (int t = 0; t < 10; t++) { g[t] = gacc[t] + glob_b2[0]; m = fmaxf(m, g[t]); }
        float s = 0.f;
        for (int t = 0; t < 10; t++) { g[t] = expf(g[t] - m); s += g[t]; }
        for (int t = 0; t < 10; t++) gam[t] = g[t] / s;
    }
    __syncthreads();

    for (int k = tid; k < 1024; k += 256) {
        float m2 = 0.f;
        #pragma unroll
        for (int t = 0; t < 10; t++) m2 += gam[t] * g_embs[t * 1024 + k];
        Msh[k] = m2;
    }
    if (a_off >= 0) {
        for (int n = tid; n < NINST; n += 256) {
            float a = 0.f;
            #pragma unroll
            for (int t = 0; t < 10; t++) a += gam[t] * g_betas[t * NINST + n];
            out[a_off + n] = a;
        }
    }
    __syncthreads();

    float l0 = 0.f, l1 = 0.f;
    for (int k = tid; k < 1024; k += 256) {
        float mv = Msh[k];
        l0 += mv * cls_w[k];
        l1 += mv * cls_w[1024 + k];
    }
    l0 = warp_sum(l0); l1 = warp_sum(l1);
    if (lane == 0) { r0s[warp] = l0; r1s[warp] = l1; }
    __syncthreads();
    if (tid == 0) {
        float L0 = cls_b[0], L1 = cls_b[1];
        for (int w = 0; w < 8; w++) { L0 += r0s[w]; L1 += r1s[w]; }
        float p0 = 1.f / (1.f + expf(-L0));
        float p1 = 1.f / (1.f + expf(-L1));
        out[0] = p0;
        if (out_size > 1) out[1] = p1;
        if (out_size > 2) out[2] = (p1 > p0) ? 1.f : 0.f;  // argmax (first-max on tie)
    }
}

// ---------------- launch ----------------
extern "C" void kernel_launch(void* const* d_in, const int* in_sizes, int n_in,
                              void* d_out, int out_size)
{
    const float* x       = (const float*)d_in[0];
    const int*   pos     = (const int*)  d_in[1];
    const float* conv1_w = (const float*)d_in[2];
    const float* conv1_b = (const float*)d_in[3];
    const float* conv2_w = (const float*)d_in[4];
    const float* conv2_b = (const float*)d_in[5];
    const float* fc1_w   = (const float*)d_in[6];
    const float* fc1_b   = (const float*)d_in[7];
    const float* fc2_w   = (const float*)d_in[8];
    const float* fc2_b   = (const float*)d_in[9];
    const float* nbr_w   = (const float*)d_in[10];
    const float* nbr_b   = (const float*)d_in[11];
    const float* tmpl    = (const float*)d_in[12];
    const float* proto_w = (const float*)d_in[13];
    const float* proto_b = (const float*)d_in[14];
    const float* glob_w1 = (const float*)d_in[15];
    const float* glob_b1 = (const float*)d_in[16];
    const float* glob_w2 = (const float*)d_in[17];
    const float* glob_b2 = (const float*)d_in[18];
    const float* cls_w   = (const float*)d_in[19];
    const float* cls_b   = (const float*)d_in[20];

    float *pF, *pH1, *pAn, *pH2, *pP;
    cudaGetSymbolAddress((void**)&pF,  g_F);
    cudaGetSymbolAddress((void**)&pH1, g_H1);
    cudaGetSymbolAddress((void**)&pAn, g_An);
    cudaGetSymbolAddress((void**)&pH2, g_H2);
    cudaGetSymbolAddress((void**)&pP,  g_P);

    const int conv_smem = 24208 * 4;  // 96832 B -> 2 blocks/SM
    cudaFuncSetAttribute(conv_kernel, cudaFuncAttributeMaxDynamicSharedMemorySize, conv_smem);

    w2t_kernel<<<61, 256>>>(conv2_w);
    conv_kernel<<<NINST, 256, conv_smem>>>(x, conv1_w, conv1_b, conv2_b);

    // fc1: relu(F @ fc1_w^T + b) -> H1
    gemm_kernel<1><<<dim3(512 / 64, NINST / 128), 256>>>(pF, fc1_w, fc1_b, pH1, 1728, 1728, 512);
    // fc2: relu(H1 @ fc2_w^T + b) -> H2[:, :512]
    gemm_kernel<1><<<dim3(512 / 64, NINST / 128), 256>>>(pH1, fc2_w, fc2_b, pH2, 512, 512, 1024);
    // An = tanh(H @ nbr_w^T + b)
    gemm_kernel<2><<<dim3(512 / 64, NINST / 128), 256>>>(pH2, nbr_w, nbr_b, pAn, 512, 1024, 512);
    // neighbor attention -> H2[:, 512:]
    nbr_kernel<<<NINST / 8, 256>>>(pos);
    // P = tanh(H2 @ proto_w^T + b)
    gemm_kernel<2><<<dim3(1024 / 64, NINST / 128), 256>>>(pH2, proto_w, proto_b, pP, 1024, 1024, 1024);
    // S, betas, embs
    s_kernel<<<NINST, 256>>>(tmpl);
    betas_kernel<<<10, 256>>>();
    embs_kernel<<<dim3(4, 10), 256>>>();
    // global attention + classifier + write outputs
    final_kernel<<<1, 256>>>(glob_w1, glob_b1, glob_w2, glob_b2, cls_w, cls_b,
                             (float*)d_out, out_size - NINST, out_size);
}

// round 12
// speedup vs baseline: 1.2664x; 1.0110x over previous
#include <cuda_runtime.h>
#include <math.h>

#define NINST 2048

// ---------------- scratch (no allocation allowed -> __device__ globals) ----------------
__device__ float g_F[NINST * 1728];   // CNN features
__device__ float g_H1[NINST * 512];   // fc1 out
__device__ float g_An[NINST * 512];   // tanh(H @ nbr_w^T + b)
__device__ float g_H2[NINST * 1024];  // [:, :512] = H (fc2 out), [:, 512:] = Hn
__device__ float g_P[NINST * 1024];   // tanh(H2 @ proto_w^T + b)
__device__ float g_S[NINST * 10];     // P @ templates^T   (n-major)
__device__ float g_betas[10 * NINST];
__device__ float g_embs[10 * 1024];
__device__ float g_w2t[15552];        // conv2 weights transposed to [ic][ky][kx][oc]

typedef unsigned long long u64;

// ---- packed f32x2 helpers (Blackwell FFMA2: 2 fp32 FMAs per issue slot) ----
__device__ __forceinline__ u64 pack2(float lo, float hi) {
    u64 r;
    asm("mov.b64 %0, {%1, %2};" : "=l"(r) : "f"(lo), "f"(hi));
    return r;
}
__device__ __forceinline__ void unpack2(u64 v, float& lo, float& hi) {
    asm("mov.b64 {%0, %1}, %2;" : "=f"(lo), "=f"(hi) : "l"(v));
}
__device__ __forceinline__ u64 fma2(u64 a, u64 b, u64 c) {
    u64 d;
    asm("fma.rn.f32x2 %0, %1, %2, %3;" : "=l"(d) : "l"(a), "l"(b), "l"(c));
    return d;
}

__device__ __forceinline__ float warp_sum(float v) {
    #pragma unroll
    for (int o = 16; o; o >>= 1) v += __shfl_xor_sync(0xffffffffu, v, o);
    return v;
}
__device__ __forceinline__ float warp_max(float v) {
    #pragma unroll
    for (int o = 16; o; o >>= 1) v = fmaxf(v, __shfl_xor_sync(0xffffffffu, v, o));
    return v;
}

// ---------------- one-shot conv2 weight transpose: [oc][ic][ky][kx] -> [ic][ky][kx][oc] ----------------
__global__ void w2t_kernel(const float* __restrict__ w2)
{
    int i = blockIdx.x * 256 + threadIdx.x;
    if (i < 15552) {
        int oc = i % 48; int r = i / 48;
        int kx = r % 3, ky = (r / 3) % 3, ic = r / 9;
        g_w2t[i] = w2[oc * 324 + ic * 9 + ky * 3 + kx];
    }
}

// ---------------- fused per-instance CNN: conv1+relu+pool, conv2+relu+pool(in regs) ----------------
// grid = 2048 blocks, 256 threads, 96.8KB dynamic smem -> 2 blocks/SM
__global__ void __launch_bounds__(256) conv_kernel(
    const float* __restrict__ x,
    const float* __restrict__ w1, const float* __restrict__ b1,
    const float* __restrict__ b2)
{
    extern __shared__ float sm[];
    float* xin = sm;            // 1024   (32x32 input)
    float* c1w = sm + 1024;     // 576    (36x1x4x4)
    float* p1  = sm + 1600;     // 7056   (36x14x14 pooled)
    float* w2s = sm + 8656;     // 15552  conv2 weights [ic][ky][kx][oc] (pre-transposed)

    const int n = blockIdx.x, tid = threadIdx.x;
    const float* xsrc = x + (size_t)n * 1024;
    for (int i = tid; i < 1024; i += 256) xin[i] = xsrc[i];
    for (int i = tid; i < 576;  i += 256) c1w[i] = w1[i];
    for (int i = tid; i < 15552; i += 256) w2s[i] = g_w2t[i];
    __syncthreads();

    // conv1 (4x4, VALID -> 29x29) + relu + 2x2 maxpool -> 36 x 14 x 14
    // f32x2 over the pool-dx pair: acc2[dy] holds {sum(dx=0), sum(dx=1)}
    for (int o = tid; o < 7056; o += 256) {
        int c = o / 196, rem = o % 196, py = rem / 14, px = rem % 14;
        int y0 = 2 * py, xx0 = 2 * px;
        float patch[5][5];
        #pragma unroll
        for (int r = 0; r < 5; r++)
            #pragma unroll
            for (int cc = 0; cc < 5; cc++) patch[r][cc] = xin[(y0 + r) * 32 + xx0 + cc];
        // pair packs: pr[r][kx] = {patch[r][kx], patch[r][kx+1]}
        u64 pr[5][4];
        #pragma unroll
        for (int r = 0; r < 5; r++)
            #pragma unroll
            for (int kx = 0; kx < 4; kx++) pr[r][kx] = pack2(patch[r][kx], patch[r][kx + 1]);
        const float* wc = &c1w[c * 16];
        u64 acc2[2];
        acc2[0] = pack2(0.f, 0.f); acc2[1] = acc2[0];
        #pragma unroll
        for (int ky = 0; ky < 4; ky++)
            #pragma unroll
            for (int kx = 0; kx < 4; kx++) {
                float w = wc[ky * 4 + kx];
                u64 ww = pack2(w, w);
                acc2[0] = fma2(pr[ky][kx],     ww, acc2[0]);
                acc2[1] = fma2(pr[ky + 1][kx], ww, acc2[1]);
            }
        float s00, s01, s10, s11;
        unpack2(acc2[0], s00, s01);
        unpack2(acc2[1], s10, s11);
        float m = fmaxf(fmaxf(s00, s01), fmaxf(s10, s11));
        p1[o] = fmaxf(m + b1[c], 0.f);  // relu(max(conv)+b) == max(relu(conv+b))
    }
    __syncthreads();

    // conv2 (3x3, 36->48, VALID -> 12x12) + relu + 2x2 maxpool, registers + f32x2 over oc-pairs.
    // 216 items: each computes 2 conv rows x 4 conv cols x 4 ocs -> 2x4=8 pooled outputs.
    if (tid < 216) {
        const int ocg = tid / 18, rem = tid % 18, py = rem / 3, xg = rem % 3;
        const int oc0 = ocg * 4, y0 = 2 * py, x0 = 4 * xg;
        u64 acc01[2][4], acc23[2][4];   // [yy][xi], pairs (oc0,oc0+1) and (oc0+2,oc0+3)
        const u64 z = pack2(0.f, 0.f);
        #pragma unroll
        for (int yy = 0; yy < 2; yy++)
            #pragma unroll
            for (int xi = 0; xi < 4; xi++) { acc01[yy][xi] = z; acc23[yy][xi] = z; }

        for (int ic = 0; ic < 36; ic++) {
            float in[4][6];
            #pragma unroll
            for (int r = 0; r < 4; r++) {
                const float* row = &p1[ic * 196 + (y0 + r) * 14 + x0];
                #pragma unroll
                for (int c = 0; c < 6; c++) in[r][c] = row[c];
            }
            #pragma unroll
            for (int ky = 0; ky < 3; ky++) {
                #pragma unroll
                for (int kx = 0; kx < 3; kx++) {
                    float4 wv = *(const float4*)&w2s[((ic * 3 + ky) * 3 + kx) * 48 + oc0];
                    u64 w01 = pack2(wv.x, wv.y);
                    u64 w23 = pack2(wv.z, wv.w);
                    #pragma unroll
                    for (int yy = 0; yy < 2; yy++)
                        #pragma unroll
                        for (int xi = 0; xi < 4; xi++) {
                            float v = in[yy + ky][kx + xi];
                            u64 vv = pack2(v, v);
                            acc01[yy][xi] = fma2(vv, w01, acc01[yy][xi]);
                            acc23[yy][xi] = fma2(vv, w23, acc23[yy][xi]);
                        }
                }
            }
        }
        // unpack, bias + relu + pool, write flattened (c*36 + y*6 + x)
        float a[2][4][4];
        #pragma unroll
        for (int yy = 0; yy < 2; yy++)
            #pragma unroll
            for (int xi = 0; xi < 4; xi++) {
                unpack2(acc01[yy][xi], a[yy][xi][0], a[yy][xi][1]);
                unpack2(acc23[yy][xi], a[yy][xi][2], a[yy][xi][3]);
            }
        float* Fo = g_F + (size_t)n * 1728;
        #pragma unroll
        for (int oj = 0; oj < 4; oj++) {
            float bb = b2[oc0 + oj];
            #pragma unroll
            for (int px = 0; px < 2; px++) {
                float m = fmaxf(fmaxf(a[0][2 * px][oj], a[0][2 * px + 1][oj]),
                                fmaxf(a[1][2 * px][oj], a[1][2 * px + 1][oj]));
                Fo[(oc0 + oj) * 36 + py * 6 + 2 * xg + px] = fmaxf(m + bb, 0.f);
            }
        }
    }
}

// ---------------- tiled SGEMM: C[M,N] = act(A[M,K] @ W[N,K]^T + bias) ----------------
// BM=128, BN=64, BK=16, 256 threads, 8x4 microtile (f32x2 pairs), register-prefetch.
// M mult of 128, N mult of 64, K mult of 16. ACT: 0 none, 1 relu, 2 tanh
template <int ACT>
__global__ void __launch_bounds__(256) gemm_kernel(
    const float* __restrict__ A, const float* __restrict__ W,
    const float* __restrict__ bias, float* __restrict__ C,
    int K, int lda, int ldc)
{
    __shared__ float As[16][132];   // padded, 132*4 % 16 == 0 keeps float4 alignment
    __shared__ float Ws[16][68];
    const int tid = threadIdx.x;
    const int tx = tid & 15, ty = tid >> 4;
    const int row0 = blockIdx.y * 128, col0 = blockIdx.x * 64;
    const int lm = tid >> 2;            // 0..63
    const int lk = (tid & 3) * 4;       // 0,4,8,12
    const float* Ab0 = A + (size_t)(row0 + lm) * lda + lk;
    const float* Ab1 = A + (size_t)(row0 + lm + 64) * lda + lk;
    const float* Wb  = W + (size_t)(col0 + lm) * K + lk;

    u64 acc01[8], acc23[8];             // col pairs (tx*4+0,1) and (tx*4+2,3) for 8 rows
    const u64 z = pack2(0.f, 0.f);
    #pragma unroll
    for (int i = 0; i < 8; i++) { acc01[i] = z; acc23[i] = z; }

    // prefetch first tile
    float4 av0 = *(const float4*)(Ab0);
    float4 av1 = *(const float4*)(Ab1);
    float4 wv  = *(const float4*)(Wb);

    for (int k0 = 0; k0 < K; k0 += 16) {
        As[lk + 0][lm] = av0.x; As[lk + 1][lm] = av0.y; As[lk + 2][lm] = av0.z; As[lk + 3][lm] = av0.w;
        As[lk + 0][lm + 64] = av1.x; As[lk + 1][lm + 64] = av1.y; As[lk + 2][lm + 64] = av1.z; As[lk + 3][lm + 64] = av1.w;
        Ws[lk + 0][lm] = wv.x; Ws[lk + 1][lm] = wv.y; Ws[lk + 2][lm] = wv.z; Ws[lk + 3][lm] = wv.w;
        __syncthreads();
        if (k0 + 16 < K) {
            av0 = *(const float4*)(Ab0 + k0 + 16);
            av1 = *(const float4*)(Ab1 + k0 + 16);
            wv  = *(const float4*)(Wb  + k0 + 16);
        }
        #pragma unroll
        for (int k = 0; k < 16; k++) {
            float4 a0 = *(const float4*)&As[k][ty * 8];
            float4 a1 = *(const float4*)&As[k][ty * 8 + 4];
            float4 b  = *(const float4*)&Ws[k][tx * 4];
            u64 b01 = pack2(b.x, b.y);
            u64 b23 = pack2(b.z, b.w);
            float ar[8] = {a0.x, a0.y, a0.z, a0.w, a1.x, a1.y, a1.z, a1.w};
            #pragma unroll
            for (int i = 0; i < 8; i++) {
                u64 aa = pack2(ar[i], ar[i]);
                acc01[i] = fma2(aa, b01, acc01[i]);
                acc23[i] = fma2(aa, b23, acc23[i]);
            }
        }
        __syncthreads();
    }

    float4 bv = *(const float4*)&bias[col0 + tx * 4];
    #pragma unroll
    for (int i = 0; i < 8; i++) {
        float c0, c1, c2, c3;
        unpack2(acc01[i], c0, c1);
        unpack2(acc23[i], c2, c3);
        float v0 = c0 + bv.x, v1 = c1 + bv.y, v2 = c2 + bv.z, v3 = c3 + bv.w;
        if (ACT == 1) { v0 = fmaxf(v0, 0.f); v1 = fmaxf(v1, 0.f); v2 = fmaxf(v2, 0.f); v3 = fmaxf(v3, 0.f); }
        if (ACT == 2) { v0 = tanhf(v0); v1 = tanhf(v1); v2 = tanhf(v2); v3 = tanhf(v3); }
        float4 ov = make_float4(v0, v1, v2, v3);
        *(float4*)&C[(size_t)(row0 + ty * 8 + i) * ldc + col0 + tx * 4] = ov;
    }
}

// ---------------- neighbor attention: only the <=8 grid neighbors matter ----------------
// warp per instance; logits[i,j] = H[i] . An[j]; softmax over neighbors; Hn[i] = sum a_j H[j]
__global__ void __launch_bounds__(256) nbr_kernel(const int* __restrict__ positions)
{
    const int warp = threadIdx.x >> 5, lane = threadIdx.x & 31;
    const int i = blockIdx.x * 8 + warp;
    if (i >= NINST) return;
    const int pr = positions[2 * i], pc = positions[2 * i + 1];

    float hi[16];
    #pragma unroll
    for (int q = 0; q < 16; q++) hi[q] = g_H2[(size_t)i * 1024 + lane + q * 32];

    const int dr[8] = {-1, -1, -1, 0, 0, 1, 1, 1};
    const int dc[8] = {-1, 0, 1, -1, 1, -1, 0, 1};
    float lg[8]; int js[8]; int cnt = 0;
    for (int d = 0; d < 8; d++) {
        int nr = pr + dr[d], nc = pc + dc[d];
        if (nr < 0 || nr >= 32 || nc < 0 || nc >= 64) continue;
        int j = nr * 64 + nc;
        const float* an = &g_An[(size_t)j * 512];
        float s = 0.f;
        #pragma unroll
        for (int q = 0; q < 16; q++) s += hi[q] * an[lane + q * 32];
        s = warp_sum(s);
        js[cnt] = j; lg[cnt] = s; cnt++;
    }
    if (cnt == 0) {  // fallback (dead code for this grid, kept for faithfulness)
        const float* an = &g_An[(size_t)i * 512];
        float s = 0.f;
        #pragma unroll
        for (int q = 0; q < 16; q++) s += hi[q] * an[lane + q * 32];
        lg[0] = warp_sum(s); js[0] = i; cnt = 1;
    }
    float m = -1e30f;
    for (int d = 0; d < cnt; d++) m = fmaxf(m, lg[d]);
    float ssum = 0.f;
    for (int d = 0; d < cnt; d++) { lg[d] = expf(lg[d] - m); ssum += lg[d]; }
    float inv = 1.f / ssum;
    #pragma unroll
    for (int q = 0; q < 16; q++) {
        int k = lane + q * 32;
        float a = 0.f;
        for (int d = 0; d < cnt; d++) a += lg[d] * g_H2[(size_t)js[d] * 1024 + k];
        g_H2[(size_t)i * 1024 + 512 + k] = a * inv;
    }
}

// ---------------- S[n][t] = P[n] . templates[t]  (TEMP folded in) ----------------
__global__ void __launch_bounds__(256) s_kernel(const float* __restrict__ tmpl)
{
    const int n = blockIdx.x, tid = threadIdx.x;
    float s[10];
    #pragma unroll
    for (int t = 0; t < 10; t++) s[t] = 0.f;
    for (int k = tid; k < 1024; k += 256) {
        float p = g_P[(size_t)n * 1024 + k];
        #pragma unroll
        for (int t = 0; t < 10; t++) s[t] += p * __ldg(&tmpl[t * 1024 + k]);
    }
    __shared__ float red[8][10];
    #pragma unroll
    for (int t = 0; t < 10; t++) s[t] = warp_sum(s[t]);
    if ((tid & 31) == 0) {
        #pragma unroll
        for (int t = 0; t < 10; t++) red[tid >> 5][t] = s[t];
    }
    __syncthreads();
    if (tid < 10) {
        float v = 0.f;
        #pragma unroll
        for (int w = 0; w < 8; w++) v += red[w][tid];
        g_S[n * 10 + tid] = v;  // / TEMP (== 1.0)
    }
}

// ---------------- betas[t][:] = softmax_n(S[:,t]) ----------------
__global__ void __launch_bounds__(256) betas_kernel()
{
    const int t = blockIdx.x, tid = threadIdx.x;
    __shared__ float red[32];
    float m = -1e30f;
    for (int n = tid; n < NINST; n += 256) m = fmaxf(m, g_S[n * 10 + t]);
    m = warp_max(m);
    if ((tid & 31) == 0) red[tid >> 5] = m;
    __syncthreads();
    if (tid < 32) { float v = (tid < 8) ? red[tid] : -1e30f; v = warp_max(v); if (tid == 0) red[0] = v; }
    __syncthreads();
    m = red[0];
    __syncthreads();
    float s = 0.f;
    for (int n = tid; n < NINST; n += 256) {
        float e = expf(g_S[n * 10 + t] - m);
        g_betas[t * NINST + n] = e;
        s += e;
    }
    s = warp_sum(s);
    if ((tid & 31) == 0) red[tid >> 5] = s;
    __syncthreads();
    if (tid < 32) { float v = (tid < 8) ? red[tid] : 0.f; v = warp_sum(v); if (tid == 0) red[0] = v; }
    __syncthreads();
    float inv = 1.f / red[0];
    for (int n = tid; n < NINST; n += 256) g_betas[t * NINST + n] *= inv;
}

// ---------------- embs[t] = betas[t] @ H2 ----------------
__global__ void __launch_bounds__(256) embs_kernel()
{
    const int t = blockIdx.y;
    const int k = blockIdx.x * 256 + threadIdx.x;
    __shared__ float bsh[256];
    float acc = 0.f;
    for (int n0 = 0; n0 < NINST; n0 += 256) {
        __syncthreads();
        bsh[threadIdx.x] = g_betas[t * NINST + n0 + threadIdx.x];
        __syncthreads();
        #pragma unroll 4
        for (int nn = 0; nn < 256; nn++) acc += bsh[nn] * g_H2[(size_t)(n0 + nn) * 1024 + k];
    }
    g_embs[t * 1024 + k] = acc;
}

// ---------------- global attention + classifier + outputs ----------------
__global__ void __launch_bounds__(256) final_kernel(
    const float* __restrict__ glob_w1, const float* __restrict__ glob_b1,
    const float* __restrict__ glob_w2, const float* __restrict__ glob_b2,
    const float* __restrict__ cls_w, const float* __restrict__ cls_b,
    float* __restrict__ out, int a_off, int out_size)
{
    const int tid = threadIdx.x, warp = tid >> 5, lane = tid & 31;
    __shared__ float gacc[10];
    __shared__ float gam[10];
    __shared__ float Msh[1024];
    __shared__ float r0s[8], r1s[8];
    if (tid < 10) gacc[tid] = 0.f;
    __syncthreads();

    for (int t = 0; t < 10; t++) {
        const float* e = &g_embs[t * 1024];
        for (int o = warp; o < 128; o += 8) {
            const float* wrow = &glob_w1[o * 1024];
            float s = 0.f;
            for (int k = lane; k < 1024; k += 32) s += e[k] * wrow[k];
            s = warp_sum(s);
            if (lane == 0) atomicAdd(&gacc[t], tanhf(s + glob_b1[o]) * glob_w2[o]);
        }
    }
    __syncthreads();
    if (tid == 0) {
        float g[10], m = -1e30f;
        for (int t = 0; t < 10; t++) { g[t] = gacc[t] + glob_b2[0]; m = fmaxf(m, g[t]); }
        float s = 0.f;
        for (int t = 0; t < 10; t++) { g[t] = expf(g[t] - m); s += g[t]; }
        for (int t = 0; t < 10; t++) gam[t] = g[t] / s;
    }
    __syncthreads();

    for (int k = tid; k < 1024; k += 256) {
        float m2 = 0.f;
        #pragma unroll
        for (int t = 0; t < 10; t++) m2 += gam[t] * g_embs[t * 1024 + k];
        Msh[k] = m2;
    }
    if (a_off >= 0) {
        for (int n = tid; n < NINST; n += 256) {
            float a = 0.f;
            #pragma unroll
            for (int t = 0; t < 10; t++) a += gam[t] * g_betas[t * NINST + n];
            out[a_off + n] = a;
        }
    }
    __syncthreads();

    float l0 = 0.f, l1 = 0.f;
    for (int k = tid; k < 1024; k += 256) {
        float mv = Msh[k];
        l0 += mv * cls_w[k];
        l1 += mv * cls_w[1024 + k];
    }
    l0 = warp_sum(l0); l1 = warp_sum(l1);
    if (lane == 0) { r0s[warp] = l0; r1s[warp] = l1; }
    __syncthreads();
    if (tid == 0) {
        float L0 = cls_b[0], L1 = cls_b[1];
        for (int w = 0; w < 8; w++) { L0 += r0s[w]; L1 += r1s[w]; }
        float p0 = 1.f / (1.f + expf(-L0));
        float p1 = 1.f / (1.f + expf(-L1));
        out[0] = p0;
        if (out_size > 1) out[1] = p1;
        if (out_size > 2) out[2] = (p1 > p0) ? 1.f : 0.f;  // argmax (first-max on tie)
    }
}

// ---------------- launch ----------------
extern "C" void kernel_launch(void* const* d_in, const int* in_sizes, int n_in,
                              void* d_out, int out_size)
{
    const float* x       = (const float*)d_in[0];
    const int*   pos     = (const int*)  d_in[1];
    const float* conv1_w = (const float*)d_in[2];
    const float* conv1_b = (const float*)d_in[3];
    const float* conv2_w = (const float*)d_in[4];
    const float* conv2_b = (const float*)d_in[5];
    const float* fc1_w   = (const float*)d_in[6];
    const float* fc1_b   = (const float*)d_in[7];
    const float* fc2_w   = (const float*)d_in[8];
    const float* fc2_b   = (const float*)d_in[9];
    const float* nbr_w   = (const float*)d_in[10];
    const float* nbr_b   = (const float*)d_in[11];
    const float* tmpl    = (const float*)d_in[12];
    const float* proto_w = (const float*)d_in[13];
    const float* proto_b = (const float*)d_in[14];
    const float* glob_w1 = (const float*)d_in[15];
    const float* glob_b1 = (const float*)d_in[16];
    const float* glob_w2 = (const float*)d_in[17];
    const float* glob_b2 = (const float*)d_in[18];
    const float* cls_w   = (const float*)d_in[19];
    const float* cls_b   = (const float*)d_in[20];

    float *pF, *pH1, *pAn, *pH2, *pP;
    cudaGetSymbolAddress((void**)&pF,  g_F);
    cudaGetSymbolAddress((void**)&pH1, g_H1);
    cudaGetSymbolAddress((void**)&pAn, g_An);
    cudaGetSymbolAddress((void**)&pH2, g_H2);
    cudaGetSymbolAddress((void**)&pP,  g_P);

    const int conv_smem = 24208 * 4;  // 96832 B -> 2 blocks/SM
    cudaFuncSetAttribute(conv_kernel, cudaFuncAttributeMaxDynamicSharedMemorySize, conv_smem);

    w2t_kernel<<<61, 256>>>(conv2_w);
    conv_kernel<<<NINST, 256, conv_smem>>>(x, conv1_w, conv1_b, conv2_b);

    // fc1: relu(F @ fc1_w^T + b) -> H1
    gemm_kernel<1><<<dim3(512 / 64, NINST / 128), 256>>>(pF, fc1_w, fc1_b, pH1, 1728, 1728, 512);
    // fc2: relu(H1 @ fc2_w^T + b) -> H2[:, :512]
    gemm_kernel<1><<<dim3(512 / 64, NINST / 128), 256>>>(pH1, fc2_w, fc2_b, pH2, 512, 512, 1024);
    // An = tanh(H @ nbr_w^T + b)
    gemm_kernel<2><<<dim3(512 / 64, NINST / 128), 256>>>(pH2, nbr_w, nbr_b, pAn, 512, 1024, 512);
    // neighbor attention -> H2[:, 512:]
    nbr_kernel<<<NINST / 8, 256>>>(pos);
    // P = tanh(H2 @ proto_w^T + b)
    gemm_kernel<2><<<dim3(1024 / 64, NINST / 128), 256>>>(pH2, proto_w, proto_b, pP, 1024, 1024, 1024);
    // S, betas, embs
    s_kernel<<<NINST, 256>>>(tmpl);
    betas_kernel<<<10, 256>>>();
    embs_kernel<<<dim3(4, 10), 256>>>();
    // global attention + classifier + write outputs
    final_kernel<<<1, 256>>>(glob_w1, glob_b1, glob_w2, glob_b2, cls_w, cls_b,
                             (float*)d_out, out_size - NINST, out_size);
}

// round 15
// speedup vs baseline: 1.2740x; 1.0060x over previous
#include <cuda_runtime.h>
#include <math.h>

#define NINST 2048

// ---------------- scratch (no allocation allowed -> __device__ globals) ----------------
__device__ float g_F[NINST * 1728];   // CNN features
__device__ float g_H1[NINST * 512];   // fc1 out
__device__ float g_An[NINST * 512];   // tanh(H @ nbr_w^T + b)
__device__ float g_H2[NINST * 1024];  // [:, :512] = H (fc2 out), [:, 512:] = Hn
__device__ float g_P[NINST * 1024];   // tanh(H2 @ proto_w^T + b)
__device__ float g_S[NINST * 10];     // P @ templates^T   (n-major)
__device__ float g_betas[10 * NINST];
__device__ float g_embs[10 * 1024];
__device__ float g_w2t[15552];        // conv2 weights transposed to [ic][ky][kx][oc]

typedef unsigned long long u64;

// ---- packed f32x2 helpers (Blackwell FFMA2: 2 fp32 FMAs per issue slot) ----
__device__ __forceinline__ u64 pack2(float lo, float hi) {
    u64 r;
    asm("mov.b64 %0, {%1, %2};" : "=l"(r) : "f"(lo), "f"(hi));
    return r;
}
__device__ __forceinline__ void unpack2(u64 v, float& lo, float& hi) {
    asm("mov.b64 {%0, %1}, %2;" : "=f"(lo), "=f"(hi) : "l"(v));
}
__device__ __forceinline__ u64 fma2(u64 a, u64 b, u64 c) {
    u64 d;
    asm("fma.rn.f32x2 %0, %1, %2, %3;" : "=l"(d) : "l"(a), "l"(b), "l"(c));
    return d;
}

__device__ __forceinline__ float warp_sum(float v) {
    #pragma unroll
    for (int o = 16; o; o >>= 1) v += __shfl_xor_sync(0xffffffffu, v, o);
    return v;
}
__device__ __forceinline__ float warp_max(float v) {
    #pragma unroll
    for (int o = 16; o; o >>= 1) v = fmaxf(v, __shfl_xor_sync(0xffffffffu, v, o));
    return v;
}

// ---------------- one-shot conv2 weight transpose: [oc][ic][ky][kx] -> [ic][ky][kx][oc] ----------------
__global__ void w2t_kernel(const float* __restrict__ w2)
{
    int i = blockIdx.x * 256 + threadIdx.x;
    if (i < 15552) {
        int oc = i % 48; int r = i / 48;
        int kx = r % 3, ky = (r / 3) % 3, ic = r / 9;
        g_w2t[i] = w2[oc * 324 + ic * 9 + ky * 3 + kx];
    }
}

// ---------------- fused per-instance CNN: conv1+relu+pool, conv2+relu+pool(in regs) ----------------
// grid = 2048 blocks, 256 threads, 34.6KB dynamic smem -> occupancy now reg-limited (3-4 blocks/SM)
// conv2 weights read via __ldg from g_w2t (62KB, L1-resident per SM; each float4 reused 18x/block)
__global__ void __launch_bounds__(256) conv_kernel(
    const float* __restrict__ x,
    const float* __restrict__ w1, const float* __restrict__ b1,
    const float* __restrict__ b2)
{
    extern __shared__ float sm[];
    float* xin = sm;            // 1024   (32x32 input)
    float* c1w = sm + 1024;     // 576    (36x1x4x4)
    float* p1  = sm + 1600;     // 7056   (36x14x14 pooled)  -> 8656 floats = 34624 B

    const int n = blockIdx.x, tid = threadIdx.x;
    const float* xsrc = x + (size_t)n * 1024;
    for (int i = tid; i < 1024; i += 256) xin[i] = xsrc[i];
    for (int i = tid; i < 576;  i += 256) c1w[i] = w1[i];
    __syncthreads();

    // conv1 (4x4, VALID -> 29x29) + relu + 2x2 maxpool -> 36 x 14 x 14
    // f32x2 over the pool-dx pair: acc2[dy] holds {sum(dx=0), sum(dx=1)}
    for (int o = tid; o < 7056; o += 256) {
        int c = o / 196, rem = o % 196, py = rem / 14, px = rem % 14;
        int y0 = 2 * py, xx0 = 2 * px;
        float patch[5][5];
        #pragma unroll
        for (int r = 0; r < 5; r++)
            #pragma unroll
            for (int cc = 0; cc < 5; cc++) patch[r][cc] = xin[(y0 + r) * 32 + xx0 + cc];
        // pair packs: pr[r][kx] = {patch[r][kx], patch[r][kx+1]}
        u64 pr[5][4];
        #pragma unroll
        for (int r = 0; r < 5; r++)
            #pragma unroll
            for (int kx = 0; kx < 4; kx++) pr[r][kx] = pack2(patch[r][kx], patch[r][kx + 1]);
        const float* wc = &c1w[c * 16];
        u64 acc2[2];
        acc2[0] = pack2(0.f, 0.f); acc2[1] = acc2[0];
        #pragma unroll
        for (int ky = 0; ky < 4; ky++)
            #pragma unroll
            for (int kx = 0; kx < 4; kx++) {
                float w = wc[ky * 4 + kx];
                u64 ww = pack2(w, w);
                acc2[0] = fma2(pr[ky][kx],     ww, acc2[0]);
                acc2[1] = fma2(pr[ky + 1][kx], ww, acc2[1]);
            }
        float s00, s01, s10, s11;
        unpack2(acc2[0], s00, s01);
        unpack2(acc2[1], s10, s11);
        float m = fmaxf(fmaxf(s00, s01), fmaxf(s10, s11));
        p1[o] = fmaxf(m + b1[c], 0.f);  // relu(max(conv)+b) == max(relu(conv+b))
    }
    __syncthreads();

    // conv2 (3x3, 36->48, VALID -> 12x12) + relu + 2x2 maxpool, registers + f32x2 over oc-pairs.
    // 216 items: each computes 2 conv rows x 4 conv cols x 4 ocs -> 2x4=8 pooled outputs.
    // Weights via __ldg (L1-cached, reused 18x per block) instead of smem staging.
    if (tid < 216) {
        const int ocg = tid / 18, rem = tid % 18, py = rem / 3, xg = rem % 3;
        const int oc0 = ocg * 4, y0 = 2 * py, x0 = 4 * xg;
        u64 acc01[2][4], acc23[2][4];   // [yy][xi], pairs (oc0,oc0+1) and (oc0+2,oc0+3)
        const u64 z = pack2(0.f, 0.f);
        #pragma unroll
        for (int yy = 0; yy < 2; yy++)
            #pragma unroll
            for (int xi = 0; xi < 4; xi++) { acc01[yy][xi] = z; acc23[yy][xi] = z; }

        for (int ic = 0; ic < 36; ic++) {
            float in[4][6];
            #pragma unroll
            for (int r = 0; r < 4; r++) {
                const float* row = &p1[ic * 196 + (y0 + r) * 14 + x0];
                #pragma unroll
                for (int c = 0; c < 6; c++) in[r][c] = row[c];
            }
            #pragma unroll
            for (int ky = 0; ky < 3; ky++) {
                #pragma unroll
                for (int kx = 0; kx < 3; kx++) {
                    float4 wv = __ldg((const float4*)&g_w2t[((ic * 3 + ky) * 3 + kx) * 48 + oc0]);
                    u64 w01 = pack2(wv.x, wv.y);
                    u64 w23 = pack2(wv.z, wv.w);
                    #pragma unroll
                    for (int yy = 0; yy < 2; yy++)
                        #pragma unroll
                        for (int xi = 0; xi < 4; xi++) {
                            float v = in[yy + ky][kx + xi];
                            u64 vv = pack2(v, v);
                            acc01[yy][xi] = fma2(vv, w01, acc01[yy][xi]);
                            acc23[yy][xi] = fma2(vv, w23, acc23[yy][xi]);
                        }
                }
            }
        }
        // unpack, bias + relu + pool, write flattened (c*36 + y*6 + x)
        float a[2][4][4];
        #pragma unroll
        for (int yy = 0; yy < 2; yy++)
            #pragma unroll
            for (int xi = 0; xi < 4; xi++) {
                unpack2(acc01[yy][xi], a[yy][xi][0], a[yy][xi][1]);
                unpack2(acc23[yy][xi], a[yy][xi][2], a[yy][xi][3]);
            }
        float* Fo = g_F + (size_t)n * 1728;
        #pragma unroll
        for (int oj = 0; oj < 4; oj++) {
            float bb = b2[oc0 + oj];
            #pragma unroll
            for (int px = 0; px < 2; px++) {
                float m = fmaxf(fmaxf(a[0][2 * px][oj], a[0][2 * px + 1][oj]),
                                fmaxf(a[1][2 * px][oj], a[1][2 * px + 1][oj]));
                Fo[(oc0 + oj) * 36 + py * 6 + 2 * xg + px] = fmaxf(m + bb, 0.f);
            }
        }
    }
}

// ---------------- tiled SGEMM: C[M,N] = act(A[M,K] @ W[N,K]^T + bias) ----------------
// BM=128, BN=64, BK=16, 256 threads, 8x4 microtile (f32x2 pairs), register-prefetch.
// M mult of 128, N mult of 64, K mult of 16. ACT: 0 none, 1 relu, 2 tanh
template <int ACT>
__global__ void __launch_bounds__(256) gemm_kernel(
    const float* __restrict__ A, const float* __restrict__ W,
    const float* __restrict__ bias, float* __restrict__ C,
    int K, int lda, int ldc)
{
    __shared__ float As[16][132];   // padded, 132*4 % 16 == 0 keeps float4 alignment
    __shared__ float Ws[16][68];
    const int tid = threadIdx.x;
    const int tx = tid & 15, ty = tid >> 4;
    const int row0 = blockIdx.y * 128, col0 = blockIdx.x * 64;
    const int lm = tid >> 2;            // 0..63
    const int lk = (tid & 3) * 4;       // 0,4,8,12
    const float* Ab0 = A + (size_t)(row0 + lm) * lda + lk;
    const float* Ab1 = A + (size_t)(row0 + lm + 64) * lda + lk;
    const float* Wb  = W + (size_t)(col0 + lm) * K + lk;

    u64 acc01[8], acc23[8];             // col pairs (tx*4+0,1) and (tx*4+2,3) for 8 rows
    const u64 z = pack2(0.f, 0.f);
    #pragma unroll
    for (int i = 0; i < 8; i++) { acc01[i] = z; acc23[i] = z; }

    // prefetch first tile
    float4 av0 = *(const float4*)(Ab0);
    float4 av1 = *(const float4*)(Ab1);
    float4 wv  = *(const float4*)(Wb);

    for (int k0 = 0; k0 < K; k0 += 16) {
        As[lk + 0][lm] = av0.x; As[lk + 1][lm] = av0.y; As[lk + 2][lm] = av0.z; As[lk + 3][lm] = av0.w;
        As[lk + 0][lm + 64] = av1.x; As[lk + 1][lm + 64] = av1.y; As[lk + 2][lm + 64] = av1.z; As[lk + 3][lm + 64] = av1.w;
        Ws[lk + 0][lm] = wv.x; Ws[lk + 1][lm] = wv.y; Ws[lk + 2][lm] = wv.z; Ws[lk + 3][lm] = wv.w;
        __syncthreads();
        if (k0 + 16 < K) {
            av0 = *(const float4*)(Ab0 + k0 + 16);
            av1 = *(const float4*)(Ab1 + k0 + 16);
            wv  = *(const float4*)(Wb  + k0 + 16);
        }
        #pragma unroll
        for (int k = 0; k < 16; k++) {
            float4 a0 = *(const float4*)&As[k][ty * 8];
            float4 a1 = *(const float4*)&As[k][ty * 8 + 4];
            float4 b  = *(const float4*)&Ws[k][tx * 4];
            u64 b01 = pack2(b.x, b.y);
            u64 b23 = pack2(b.z, b.w);
            float ar[8] = {a0.x, a0.y, a0.z, a0.w, a1.x, a1.y, a1.z, a1.w};
            #pragma unroll
            for (int i = 0; i < 8; i++) {
                u64 aa = pack2(ar[i], ar[i]);
                acc01[i] = fma2(aa, b01, acc01[i]);
                acc23[i] = fma2(aa, b23, acc23[i]);
            }
        }
        __syncthreads();
    }

    float4 bv = *(const float4*)&bias[col0 + tx * 4];
    #pragma unroll
    for (int i = 0; i < 8; i++) {
        float c0, c1, c2, c3;
        unpack2(acc01[i], c0, c1);
        unpack2(acc23[i], c2, c3);
        float v0 = c0 + bv.x, v1 = c1 + bv.y, v2 = c2 + bv.z, v3 = c3 + bv.w;
        if (ACT == 1) { v0 = fmaxf(v0, 0.f); v1 = fmaxf(v1, 0.f); v2 = fmaxf(v2, 0.f); v3 = fmaxf(v3, 0.f); }
        if (ACT == 2) { v0 = tanhf(v0); v1 = tanhf(v1); v2 = tanhf(v2); v3 = tanhf(v3); }
        float4 ov = make_float4(v0, v1, v2, v3);
        *(float4*)&C[(size_t)(row0 + ty * 8 + i) * ldc + col0 + tx * 4] = ov;
    }
}

// ---------------- neighbor attention: only the <=8 grid neighbors matter ----------------
// warp per instance; logits[i,j] = H[i] . An[j]; softmax over neighbors; Hn[i] = sum a_j H[j]
__global__ void __launch_bounds__(256) nbr_kernel(const int* __restrict__ positions)
{
    const int warp = threadIdx.x >> 5, lane = threadIdx.x & 31;
    const int i = blockIdx.x * 8 + warp;
    if (i >= NINST) return;
    const int pr = positions[2 * i], pc = positions[2 * i + 1];

    float hi[16];
    #pragma unroll
    for (int q = 0; q < 16; q++) hi[q] = g_H2[(size_t)i * 1024 + lane + q * 32];

    const int dr[8] = {-1, -1, -1, 0, 0, 1, 1, 1};
    const int dc[8] = {-1, 0, 1, -1, 1, -1, 0, 1};
    float lg[8]; int js[8]; int cnt = 0;
    for (int d = 0; d < 8; d++) {
        int nr = pr + dr[d], nc = pc + dc[d];
        if (nr < 0 || nr >= 32 || nc < 0 || nc >= 64) continue;
        int j = nr * 64 + nc;
        const float* an = &g_An[(size_t)j * 512];
        float s = 0.f;
        #pragma unroll
        for (int q = 0; q < 16; q++) s += hi[q] * an[lane + q * 32];
        s = warp_sum(s);
        js[cnt] = j; lg[cnt] = s; cnt++;
    }
    if (cnt == 0) {  // fallback (dead code for this grid, kept for faithfulness)
        const float* an = &g_An[(size_t)i * 512];
        float s = 0.f;
        #pragma unroll
        for (int q = 0; q < 16; q++) s += hi[q] * an[lane + q * 32];
        lg[0] = warp_sum(s); js[0] = i; cnt = 1;
    }
    float m = -1e30f;
    for (int d = 0; d < cnt; d++) m = fmaxf(m, lg[d]);
    float ssum = 0.f;
    for (int d = 0; d < cnt; d++) { lg[d] = expf(lg[d] - m); ssum += lg[d]; }
    float inv = 1.f / ssum;
    #pragma unroll
    for (int q = 0; q < 16; q++) {
        int k = lane + q * 32;
        float a = 0.f;
        for (int d = 0; d < cnt; d++) a += lg[d] * g_H2[(size_t)js[d] * 1024 + k];
        g_H2[(size_t)i * 1024 + 512 + k] = a * inv;
    }
}

// ---------------- S[n][t] = P[n] . templates[t]  (TEMP folded in) ----------------
__global__ void __launch_bounds__(256) s_kernel(const float* __restrict__ tmpl)
{
    const int n = blockIdx.x, tid = threadIdx.x;
    float s[10];
    #pragma unroll
    for (int t = 0; t < 10; t++) s[t] = 0.f;
    for (int k = tid; k < 1024; k += 256) {
        float p = g_P[(size_t)n * 1024 + k];
        #pragma unroll
        for (int t = 0; t < 10; t++) s[t] += p * __ldg(&tmpl[t * 1024 + k]);
    }
    __shared__ float red[8][10];
    #pragma unroll
    for (int t = 0; t < 10; t++) s[t] = warp_sum(s[t]);
    if ((tid & 31) == 0) {
        #pragma unroll
        for (int t = 0; t < 10; t++) red[tid >> 5][t] = s[t];
    }
    __syncthreads();
    if (tid < 10) {
        float v = 0.f;
        #pragma unroll
        for (int w = 0; w < 8; w++) v += red[w][tid];
        g_S[n * 10 + tid] = v;  // / TEMP (== 1.0)
    }
}

// ---------------- betas[t][:] = softmax_n(S[:,t]) ----------------
__global__ void __launch_bounds__(256) betas_kernel()
{
    const int t = blockIdx.x, tid = threadIdx.x;
    __shared__ float red[32];
    float m = -1e30f;
    for (int n = tid; n < NINST; n += 256) m = fmaxf(m, g_S[n * 10 + t]);
    m = warp_max(m);
    if ((tid & 31) == 0) red[tid >> 5] = m;
    __syncthreads();
    if (tid < 32) { float v = (tid < 8) ? red[tid] : -1e30f; v = warp_max(v); if (tid == 0) red[0] = v; }
    __syncthreads();
    m = red[0];
    __syncthreads();
    float s = 0.f;
    for (int n = tid; n < NINST; n += 256) {
        float e = expf(g_S[n * 10 + t] - m);
        g_betas[t * NINST + n] = e;
        s += e;
    }
    s = warp_sum(s);
    if ((tid & 31) == 0) red[tid >> 5] = s;
    __syncthreads();
    if (tid < 32) { float v = (tid < 8) ? red[tid] : 0.f; v = warp_sum(v); if (tid == 0) red[0] = v; }
    __syncthreads();
    float inv = 1.f / red[0];
    for (int n = tid; n < NINST; n += 256) g_betas[t * NINST + n] *= inv;
}

// ---------------- embs[t] = betas[t] @ H2 ----------------
__global__ void __launch_bounds__(256) embs_kernel()
{
    const int t = blockIdx.y;
    const int k = blockIdx.x * 256 + threadIdx.x;
    __shared__ float bsh[256];
    float acc = 0.f;
    for (int n0 = 0; n0 < NINST; n0 += 256) {
        __syncthreads();
        bsh[threadIdx.x] = g_betas[t * NINST + n0 + threadIdx.x];
        __syncthreads();
        #pragma unroll 4
        for (int nn = 0; nn < 256; nn++) acc += bsh[nn] * g_H2[(size_t)(n0 + nn) * 1024 + k];
    }
    g_embs[t * 1024 + k] = acc;
}

// ---------------- global attention + classifier + outputs ----------------
__global__ void __launch_bounds__(256) final_kernel(
    const float* __restrict__ glob_w1, const float* __restrict__ glob_b1,
    const float* __restrict__ glob_w2, const float* __restrict__ glob_b2,
    const float* __restrict__ cls_w, const float* __restrict__ cls_b,
    float* __restrict__ out, int a_off, int out_size)
{
    const int tid = threadIdx.x, warp = tid >> 5, lane = tid & 31;
    __shared__ float gacc[10];
    __shared__ float gam[10];
    __shared__ float Msh[1024];
    __shared__ float r0s[8], r1s[8];
    if (tid < 10) gacc[tid] = 0.f;
    __syncthreads();

    for (int t = 0; t < 10; t++) {
        const float* e = &g_embs[t * 1024];
        for (int o = warp; o < 128; o += 8) {
            const float* wrow = &glob_w1[o * 1024];
            float s = 0.f;
            for (int k = lane; k < 1024; k += 32) s += e[k] * wrow[k];
            s = warp_sum(s);
            if (lane == 0) atomicAdd(&gacc[t], tanhf(s + glob_b1[o]) * glob_w2[o]);
        }
    }
    __syncthreads();
    if (tid == 0) {
        float g[10], m = -1e30f;
        for (int t = 0; t < 10; t++) { g[t] = gacc[t] + glob_b2[0]; m = fmaxf(m, g[t]); }
        float s = 0.f;
        for (int t = 0; t < 10; t++) { g[t] = expf(g[t] - m); s += g[t]; }
        for (int t = 0; t < 10; t++) gam[t] = g[t] / s;
    }
    __syncthreads();

    for (int k = tid; k < 1024; k += 256) {
        float m2 = 0.f;
        #pragma unroll
        for (int t = 0; t < 10; t++) m2 += gam[t] * g_embs[t * 1024 + k];
        Msh[k] = m2;
    }
    if (a_off >= 0) {
        for (int n = tid; n < NINST; n += 256) {
            float a = 0.f;
            #pragma unroll
            for (int t = 0; t < 10; t++) a += gam[t] * g_betas[t * NINST + n];
            out[a_off + n] = a;
        }
    }
    __syncthreads();

    float l0 = 0.f, l1 = 0.f;
    for (int k = tid; k < 1024; k += 256) {
        float mv = Msh[k];
        l0 += mv * cls_w[k];
        l1 += mv * cls_w[1024 + k];
    }
    l0 = warp_sum(l0); l1 = warp_sum(l1);
    if (lane == 0) { r0s[warp] = l0; r1s[warp] = l1; }
    __syncthreads();
    if (tid == 0) {
        float L0 = cls_b[0], L1 = cls_b[1];
        for (int w = 0; w < 8; w++) { L0 += r0s[w]; L1 += r1s[w]; }
        float p0 = 1.f / (1.f + expf(-L0));
        float p1 = 1.f / (1.f + expf(-L1));
        out[0] = p0;
        if (out_size > 1) out[1] = p1;
        if (out_size > 2) out[2] = (p1 > p0) ? 1.f : 0.f;  // argmax (first-max on tie)
    }
}

// ---------------- launch ----------------
extern "C" void kernel_launch(void* const* d_in, const int* in_sizes, int n_in,
                              void* d_out, int out_size)
{
    const float* x       = (const float*)d_in[0];
    const int*   pos     = (const int*)  d_in[1];
    const float* conv1_w = (const float*)d_in[2];
    const float* conv1_b = (const float*)d_in[3];
    const float* conv2_w = (const float*)d_in[4];
    const float* conv2_b = (const float*)d_in[5];
    const float* fc1_w   = (const float*)d_in[6];
    const float* fc1_b   = (const float*)d_in[7];
    const float* fc2_w   = (const float*)d_in[8];
    const float* fc2_b   = (const float*)d_in[9];
    const float* nbr_w   = (const float*)d_in[10];
    const float* nbr_b   = (const float*)d_in[11];
    const float* tmpl    = (const float*)d_in[12];
    const float* proto_w = (const float*)d_in[13];
    const float* proto_b = (const float*)d_in[14];
    const float* glob_w1 = (const float*)d_in[15];
    const float* glob_b1 = (const float*)d_in[16];
    const float* glob_w2 = (const float*)d_in[17];
    const float* glob_b2 = (const float*)d_in[18];
    const float* cls_w   = (const float*)d_in[19];
    const float* cls_b   = (const float*)d_in[20];

    float *pF, *pH1, *pAn, *pH2, *pP;
    cudaGetSymbolAddress((void**)&pF,  g_F);
    cudaGetSymbolAddress((void**)&pH1, g_H1);
    cudaGetSymbolAddress((void**)&pAn, g_An);
    cudaGetSymbolAddress((void**)&pH2, g_H2);
    cudaGetSymbolAddress((void**)&pP,  g_P);

    const int conv_smem = 8656 * 4;  // 34624 B -> smem allows up to 6 blocks/SM
    cudaFuncSetAttribute(conv_kernel, cudaFuncAttributeMaxDynamicSharedMemorySize, conv_smem);

    w2t_kernel<<<61, 256>>>(conv2_w);
    conv_kernel<<<NINST, 256, conv_smem>>>(x, conv1_w, conv1_b, conv2_b);

    // fc1: relu(F @ fc1_w^T + b) -> H1
    gemm_kernel<1><<<dim3(512 / 64, NINST / 128), 256>>>(pF, fc1_w, fc1_b, pH1, 1728, 1728, 512);
    // fc2: relu(H1 @ fc2_w^T + b) -> H2[:, :512]
    gemm_kernel<1><<<dim3(512 / 64, NINST / 128), 256>>>(pH1, fc2_w, fc2_b, pH2, 512, 512, 1024);
    // An = tanh(H @ nbr_w^T + b)
    gemm_kernel<2><<<dim3(512 / 64, NINST / 128), 256>>>(pH2, nbr_w, nbr_b, pAn, 512, 1024, 512);
    // neighbor attention -> H2[:, 512:]
    nbr_kernel<<<NINST / 8, 256>>>(pos);
    // P = tanh(H2 @ proto_w^T + b)
    gemm_kernel<2><<<dim3(1024 / 64, NINST / 128), 256>>>(pH2, proto_w, proto_b, pP, 1024, 1024, 1024);
    // S, betas, embs
    s_kernel<<<NINST, 256>>>(tmpl);
    betas_kernel<<<10, 256>>>();
    embs_kernel<<<dim3(4, 10), 256>>>();
    // global attention + classifier + write outputs
    final_kernel<<<1, 256>>>(glob_w1, glob_b1, glob_w2, glob_b2, cls_w, cls_b,
                             (float*)d_out, out_size - NINST, out_size);
}